// round 1
// baseline (speedup 1.0000x reference)
#include <cuda_runtime.h>
#include <cstdint>

// LmulLinear: out[m,p] = sum_k bitcast_f32(bits(x[m,k]) + bits(w[p,k]) - OFFSET) + bias[p]
// M=256, K=512, P=512. Pure ALU/FMA-pipe GEMM-alike (no tensor cores possible).

#define M_DIM 256
#define K_DIM 512
#define P_DIM 512
#define BM 32
#define BN 32
#define BK 64
#define PAD 2   // keeps 8B alignment for uint2 smem loads, breaks most bank conflicts

static __device__ __forceinline__ float u2f(uint32_t u) {
    return __uint_as_float(u);
}

__global__ __launch_bounds__(256, 1)
void lmul_linear_kernel(const float* __restrict__ x,
                        const float* __restrict__ w,
                        const float* __restrict__ bias,
                        float* __restrict__ out)
{
    constexpr uint32_t OFFSET = 1064828928u;  // 0x3F780000

    __shared__ uint32_t As[BK][BM + PAD];  // A tile, transposed: As[k][m]
    __shared__ uint32_t Bs[BK][BN + PAD];  // W tile, transposed + offset-folded: Bs[k][p]

    const int tid = threadIdx.x;
    const int tx = tid & 15;    // p-direction thread coord (0..15)
    const int ty = tid >> 4;    // m-direction thread coord (0..15)
    const int m0 = blockIdx.y * BM;
    const int p0 = blockIdx.x * BN;

    const uint32_t* __restrict__ xu = reinterpret_cast<const uint32_t*>(x);
    const uint32_t* __restrict__ wu = reinterpret_cast<const uint32_t*>(w);

    float acc00 = 0.f, acc01 = 0.f, acc10 = 0.f, acc11 = 0.f;

    // Loader mapping: 256 threads, each loads one uint4 per half-tile row group.
    // Tile is 32 rows x 64 cols: thread t -> row t/16, cols 4*(t%16)..+3; two row groups.
    const int lr = tid >> 4;           // 0..15
    const int lc = (tid & 15) * 4;     // 0,4,...,60

    for (int k0 = 0; k0 < K_DIM; k0 += BK) {
        // --- load A tile (x[m0..m0+31][k0..k0+63]), store transposed ---
        #pragma unroll
        for (int r = 0; r < BM; r += 16) {
            uint4 v = *reinterpret_cast<const uint4*>(&xu[(m0 + lr + r) * K_DIM + k0 + lc]);
            As[lc + 0][lr + r] = v.x;
            As[lc + 1][lr + r] = v.y;
            As[lc + 2][lr + r] = v.z;
            As[lc + 3][lr + r] = v.w;
        }
        // --- load W tile (w[p0..p0+31][k0..k0+63]), fold -OFFSET, store transposed ---
        #pragma unroll
        for (int r = 0; r < BN; r += 16) {
            uint4 v = *reinterpret_cast<const uint4*>(&wu[(p0 + lr + r) * K_DIM + k0 + lc]);
            Bs[lc + 0][lr + r] = v.x - OFFSET;
            Bs[lc + 1][lr + r] = v.y - OFFSET;
            Bs[lc + 2][lr + r] = v.z - OFFSET;
            Bs[lc + 3][lr + r] = v.w - OFFSET;
        }
        __syncthreads();

        // --- inner product over BK ---
        #pragma unroll
        for (int k = 0; k < BK; k++) {
            uint2 a = *reinterpret_cast<const uint2*>(&As[k][ty * 2]);
            uint2 b = *reinterpret_cast<const uint2*>(&Bs[k][tx * 2]);
            acc00 += u2f(a.x + b.x);
            acc01 += u2f(a.x + b.y);
            acc10 += u2f(a.y + b.x);
            acc11 += u2f(a.y + b.y);
        }
        __syncthreads();
    }

    const int m = m0 + ty * 2;
    const int p = p0 + tx * 2;
    const float b0 = bias[p];
    const float b1 = bias[p + 1];
    out[(m + 0) * P_DIM + p + 0] = acc00 + b0;
    out[(m + 0) * P_DIM + p + 1] = acc01 + b1;
    out[(m + 1) * P_DIM + p + 0] = acc10 + b0;
    out[(m + 1) * P_DIM + p + 1] = acc11 + b1;
}

extern "C" void kernel_launch(void* const* d_in, const int* in_sizes, int n_in,
                              void* d_out, int out_size)
{
    const float* x    = (const float*)d_in[0];   // (256, 512)
    const float* w    = (const float*)d_in[1];   // (512, 512)
    const float* bias = (const float*)d_in[2];   // (512,)
    float* out = (float*)d_out;                  // (256, 512)

    dim3 grid(P_DIM / BN, M_DIM / BM);  // (16, 8) = 128 CTAs
    dim3 block(256);
    lmul_linear_kernel<<<grid, block>>>(x, w, bias, out);
}

// round 2
// speedup vs baseline: 1.1359x; 1.1359x over previous
#include <cuda_runtime.h>
#include <cstdint>

// LmulLinear: out[m,p] = sum_k bitcast_f32(bits(x[m,k]) + bits(w[p,k]) - OFFSET) + bias[p]
// M=256, K=512, P=512. Issue-bound ALU/FMA kernel (no tensor cores possible).
//
// R2: intra-CTA split-K x2 (512 threads, 16 warps/SM) + packed f32x2 accumulation.

#define M_DIM 256
#define K_DIM 512
#define P_DIM 512
#define BM 32
#define BN 32
#define BK 64
#define PAD 2
#define GROUPS 2

__global__ __launch_bounds__(512, 1)
void lmul_linear_kernel(const float* __restrict__ x,
                        const float* __restrict__ w,
                        const float* __restrict__ bias,
                        float* __restrict__ out)
{
    constexpr uint32_t OFFSET = 1064828928u;  // 0x3F780000

    __shared__ uint32_t As[GROUPS][BK][BM + PAD];  // x tile, transposed: As[g][k][m]
    __shared__ uint32_t Bs[GROUPS][BK][BN + PAD];  // w tile, transposed + offset-folded
    __shared__ uint64_t Red[256][2];               // cross-group reduction buffer

    const int tid = threadIdx.x;
    const int g   = tid >> 8;      // k-group: 0 or 1
    const int lt  = tid & 255;     // lane within group
    const int tx  = lt & 15;       // p-direction (0..15)
    const int ty  = lt >> 4;       // m-direction (0..15)
    const int m0  = blockIdx.y * BM;
    const int p0  = blockIdx.x * BN;
    const int kbase = g * (K_DIM / GROUPS);

    const uint32_t* __restrict__ xu = reinterpret_cast<const uint32_t*>(x);
    const uint32_t* __restrict__ wu = reinterpret_cast<const uint32_t*>(w);

    // Packed f32x2 accumulators: acc0 = (out[m][p], out[m][p+1]), acc1 = row m+1.
    uint64_t acc0 = 0ull, acc1 = 0ull;  // bit pattern 0 == (0.0f, 0.0f)

    // Loader mapping within group: 256 threads, tile is 32 rows x 64 cols.
    const int lr = lt >> 4;          // 0..15
    const int lc = (lt & 15) * 4;    // 0,4,...,60

    for (int k0 = 0; k0 < K_DIM / GROUPS; k0 += BK) {
        const int kg = kbase + k0;
        // --- load x tile (rows m0.., cols kg..kg+63), store transposed ---
        #pragma unroll
        for (int r = 0; r < BM; r += 16) {
            uint4 v = *reinterpret_cast<const uint4*>(&xu[(m0 + lr + r) * K_DIM + kg + lc]);
            As[g][lc + 0][lr + r] = v.x;
            As[g][lc + 1][lr + r] = v.y;
            As[g][lc + 2][lr + r] = v.z;
            As[g][lc + 3][lr + r] = v.w;
        }
        // --- load w tile (rows p0.., cols kg..kg+63), fold -OFFSET, transposed ---
        #pragma unroll
        for (int r = 0; r < BN; r += 16) {
            uint4 v = *reinterpret_cast<const uint4*>(&wu[(p0 + lr + r) * K_DIM + kg + lc]);
            Bs[g][lc + 0][lr + r] = v.x - OFFSET;
            Bs[g][lc + 1][lr + r] = v.y - OFFSET;
            Bs[g][lc + 2][lr + r] = v.z - OFFSET;
            Bs[g][lc + 3][lr + r] = v.w - OFFSET;
        }
        __syncthreads();

        #pragma unroll
        for (int k = 0; k < BK; k++) {
            uint2 a = *reinterpret_cast<const uint2*>(&As[g][k][ty * 2]);
            uint2 b = *reinterpret_cast<const uint2*>(&Bs[g][k][tx * 2]);
            uint32_t s00 = a.x + b.x;
            uint32_t s01 = a.x + b.y;
            uint32_t s10 = a.y + b.x;
            uint32_t s11 = a.y + b.y;
            uint64_t p01, p23;
            asm("mov.b64 %0, {%1, %2};" : "=l"(p01) : "r"(s00), "r"(s01));
            asm("mov.b64 %0, {%1, %2};" : "=l"(p23) : "r"(s10), "r"(s11));
            asm("add.rn.f32x2 %0, %0, %1;" : "+l"(acc0) : "l"(p01));
            asm("add.rn.f32x2 %0, %0, %1;" : "+l"(acc1) : "l"(p23));
        }
        __syncthreads();
    }

    // --- cross-group reduction: group 1 publishes, group 0 combines + writes ---
    if (g == 1) {
        Red[lt][0] = acc0;
        Red[lt][1] = acc1;
    }
    __syncthreads();

    if (g == 0) {
        uint64_t r0 = Red[lt][0];
        uint64_t r1 = Red[lt][1];
        asm("add.rn.f32x2 %0, %0, %1;" : "+l"(acc0) : "l"(r0));
        asm("add.rn.f32x2 %0, %0, %1;" : "+l"(acc1) : "l"(r1));

        const int m = m0 + ty * 2;
        const int p = p0 + tx * 2;
        // bias pair packed once
        uint64_t bp = *reinterpret_cast<const uint64_t*>(&bias[p]);
        asm("add.rn.f32x2 %0, %0, %1;" : "+l"(acc0) : "l"(bp));
        asm("add.rn.f32x2 %0, %0, %1;" : "+l"(acc1) : "l"(bp));

        *reinterpret_cast<uint64_t*>(&out[(m + 0) * P_DIM + p]) = acc0;
        *reinterpret_cast<uint64_t*>(&out[(m + 1) * P_DIM + p]) = acc1;
    }
}

extern "C" void kernel_launch(void* const* d_in, const int* in_sizes, int n_in,
                              void* d_out, int out_size)
{
    const float* x    = (const float*)d_in[0];   // (256, 512)
    const float* w    = (const float*)d_in[1];   // (512, 512)
    const float* bias = (const float*)d_in[2];   // (512,)
    float* out = (float*)d_out;                  // (256, 512)

    dim3 grid(P_DIM / BN, M_DIM / BM);  // (16, 8) = 128 CTAs
    dim3 block(512);
    lmul_linear_kernel<<<grid, block>>>(x, w, bias, out);
}

// round 3
// speedup vs baseline: 1.3145x; 1.1572x over previous
#include <cuda_runtime.h>
#include <cstdint>

// LmulLinear: out[m,p] = sum_k bitcast_f32(bits(x[m,k]) + bits(w[p,k]) - OFFSET) + bias[p]
// M=256, K=512, P=512.
//
// R3: k-contiguous smem + LDS.128 (conflict-free via stride 132), 4x2 microtile,
//     f32x2 packed accumulation, split-K x4 within 512-thread CTA.

#define M_DIM 256
#define K_DIM 512
#define P_DIM 512
#define BM 32
#define BN 32
#define GROUPS 4
#define KG (K_DIM / GROUPS)     // 128 k's per group
#define SROW (KG + 4)           // smem row stride in words: 132 (mod 32 == 4 -> conflict-free LDS.128)
#define TPG 128                 // threads per k-group
#define TILE_WORDS (BM * SROW)  // 4224 words per tile
#define GROUP_WORDS (2 * TILE_WORDS)
#define SMEM_BYTES (GROUPS * GROUP_WORDS * 4)  // 135168 B

// acc (f32x2 pair) += ( bitcast(s0), bitcast(s1) )
#define FADD2ACC(acc, s0, s1)                                                  \
    do {                                                                       \
        uint64_t _p;                                                           \
        asm("mov.b64 %0, {%1, %2};" : "=l"(_p) : "r"(s0), "r"(s1));            \
        asm("add.rn.f32x2 %0, %0, %1;" : "+l"(acc) : "l"(_p));                 \
    } while (0)

extern __shared__ uint32_t smem[];

__global__ void __launch_bounds__(512, 1)
lmul_linear_kernel(const float* __restrict__ x,
                   const float* __restrict__ w,
                   const float* __restrict__ bias,
                   float* __restrict__ out)
{
    constexpr uint32_t OFFSET = 1064828928u;  // 0x3F780000

    const int tid = threadIdx.x;
    const int g   = tid >> 7;        // k-group 0..3
    const int lt  = tid & 127;       // lane in group
    const int tx  = lt & 15;         // p coord: cols tx, tx+16
    const int ty  = lt >> 4;         // m coord: rows ty*4 .. ty*4+3
    const int m0  = blockIdx.y * BM;
    const int p0  = blockIdx.x * BN;
    const int kg  = g * KG;

    uint32_t* As = smem + g * GROUP_WORDS;        // [BM][SROW]
    uint32_t* Bs = As + TILE_WORDS;               // [BN][SROW], offset-folded

    const uint32_t* __restrict__ xu = reinterpret_cast<const uint32_t*>(x);
    const uint32_t* __restrict__ wu = reinterpret_cast<const uint32_t*>(w);

    // ---- load tiles: 32 rows x 128 words = 1024 uint4 per tile, 8 per thread ----
    #pragma unroll
    for (int i = 0; i < 8; i++) {
        int idx = lt + i * TPG;          // 0..1023
        int row = idx >> 5;              // 32 uint4 per row
        int c   = (idx & 31) * 4;        // word col
        uint4 va = *reinterpret_cast<const uint4*>(&xu[(m0 + row) * K_DIM + kg + c]);
        *reinterpret_cast<uint4*>(&As[row * SROW + c]) = va;
        uint4 vb = *reinterpret_cast<const uint4*>(&wu[(p0 + row) * K_DIM + kg + c]);
        vb.x -= OFFSET; vb.y -= OFFSET; vb.z -= OFFSET; vb.w -= OFFSET;
        *reinterpret_cast<uint4*>(&Bs[row * SROW + c]) = vb;
    }
    __syncthreads();

    // ---- main loop: 4x2 microtile, f32x2 accumulators ----
    const uint32_t* a0p = As + (ty * 4 + 0) * SROW;
    const uint32_t* a1p = As + (ty * 4 + 1) * SROW;
    const uint32_t* a2p = As + (ty * 4 + 2) * SROW;
    const uint32_t* a3p = As + (ty * 4 + 3) * SROW;
    const uint32_t* b0p = Bs + tx * SROW;
    const uint32_t* b1p = Bs + (tx + 16) * SROW;

    uint64_t acc0 = 0ull, acc1 = 0ull, acc2 = 0ull, acc3 = 0ull;

    #pragma unroll 8
    for (int j = 0; j < KG / 4; j++) {
        uint4 b0 = *reinterpret_cast<const uint4*>(b0p + 4 * j);
        uint4 b1 = *reinterpret_cast<const uint4*>(b1p + 4 * j);

        uint4 a0 = *reinterpret_cast<const uint4*>(a0p + 4 * j);
        FADD2ACC(acc0, a0.x + b0.x, a0.x + b1.x);
        FADD2ACC(acc0, a0.y + b0.y, a0.y + b1.y);
        FADD2ACC(acc0, a0.z + b0.z, a0.z + b1.z);
        FADD2ACC(acc0, a0.w + b0.w, a0.w + b1.w);

        uint4 a1 = *reinterpret_cast<const uint4*>(a1p + 4 * j);
        FADD2ACC(acc1, a1.x + b0.x, a1.x + b1.x);
        FADD2ACC(acc1, a1.y + b0.y, a1.y + b1.y);
        FADD2ACC(acc1, a1.z + b0.z, a1.z + b1.z);
        FADD2ACC(acc1, a1.w + b0.w, a1.w + b1.w);

        uint4 a2 = *reinterpret_cast<const uint4*>(a2p + 4 * j);
        FADD2ACC(acc2, a2.x + b0.x, a2.x + b1.x);
        FADD2ACC(acc2, a2.y + b0.y, a2.y + b1.y);
        FADD2ACC(acc2, a2.z + b0.z, a2.z + b1.z);
        FADD2ACC(acc2, a2.w + b0.w, a2.w + b1.w);

        uint4 a3 = *reinterpret_cast<const uint4*>(a3p + 4 * j);
        FADD2ACC(acc3, a3.x + b0.x, a3.x + b1.x);
        FADD2ACC(acc3, a3.y + b0.y, a3.y + b1.y);
        FADD2ACC(acc3, a3.z + b0.z, a3.z + b1.z);
        FADD2ACC(acc3, a3.w + b0.w, a3.w + b1.w);
    }

    // ---- cross-group reduction (reuse group 0's tile space) ----
    uint64_t* Red = reinterpret_cast<uint64_t*>(smem);  // 3*128*4 u64 = 12 KB

    __syncthreads();   // everyone done reading tiles
    if (g > 0) {
        uint64_t* r = Red + ((g - 1) * TPG + lt) * 4;
        r[0] = acc0; r[1] = acc1; r[2] = acc2; r[3] = acc3;
    }
    __syncthreads();

    if (g == 0) {
        #pragma unroll
        for (int gg = 0; gg < 3; gg++) {
            const uint64_t* r = Red + (gg * TPG + lt) * 4;
            uint64_t r0 = r[0], r1 = r[1], r2 = r[2], r3 = r[3];
            asm("add.rn.f32x2 %0, %0, %1;" : "+l"(acc0) : "l"(r0));
            asm("add.rn.f32x2 %0, %0, %1;" : "+l"(acc1) : "l"(r1));
            asm("add.rn.f32x2 %0, %0, %1;" : "+l"(acc2) : "l"(r2));
            asm("add.rn.f32x2 %0, %0, %1;" : "+l"(acc3) : "l"(r3));
        }

        const int p = p0 + tx;
        uint32_t blo = reinterpret_cast<const uint32_t*>(bias)[p];
        uint32_t bhi = reinterpret_cast<const uint32_t*>(bias)[p + 16];
        uint64_t bp;
        asm("mov.b64 %0, {%1, %2};" : "=l"(bp) : "r"(blo), "r"(bhi));
        asm("add.rn.f32x2 %0, %0, %1;" : "+l"(acc0) : "l"(bp));
        asm("add.rn.f32x2 %0, %0, %1;" : "+l"(acc1) : "l"(bp));
        asm("add.rn.f32x2 %0, %0, %1;" : "+l"(acc2) : "l"(bp));
        asm("add.rn.f32x2 %0, %0, %1;" : "+l"(acc3) : "l"(bp));

        const int mbase = m0 + ty * 4;
        uint64_t accs[4] = {acc0, acc1, acc2, acc3};
        #pragma unroll
        for (int r = 0; r < 4; r++) {
            uint32_t lo, hi;
            asm("mov.b64 {%0, %1}, %2;" : "=r"(lo), "=r"(hi) : "l"(accs[r]));
            uint32_t* orow = reinterpret_cast<uint32_t*>(out) + (mbase + r) * P_DIM;
            orow[p]      = lo;
            orow[p + 16] = hi;
        }
    }
}

extern "C" void kernel_launch(void* const* d_in, const int* in_sizes, int n_in,
                              void* d_out, int out_size)
{
    const float* x    = (const float*)d_in[0];   // (256, 512)
    const float* w    = (const float*)d_in[1];   // (512, 512)
    const float* bias = (const float*)d_in[2];   // (512,)
    float* out = (float*)d_out;                  // (256, 512)

    cudaFuncSetAttribute(lmul_linear_kernel,
                         cudaFuncAttributeMaxDynamicSharedMemorySize, SMEM_BYTES);

    dim3 grid(P_DIM / BN, M_DIM / BM);  // (16, 8) = 128 CTAs
    lmul_linear_kernel<<<grid, 512, SMEM_BYTES>>>(x, w, bias, out);
}